// round 13
// baseline (speedup 1.0000x reference)
#include <cuda_runtime.h>
#include <cuda_bf16.h>
#include <cstdint>

// Sobel gradient magnitude, zero-padded, on [B=8, C=64, H=256, W=256] fp32.
// out = sqrt(gv^2 + gh^2 + 1e-6), gv = x[i+1,j]-x[i-1,j], gh = x[i,j+1]-x[i,j-1].
//
// Round 13: combine the two independently-isolated wins that were never
// measured together:
//   - R4 shape: 256-thread blocks, __launch_bounds__(256, 8) -> best achieved
//     occupancy of any variant (78.0%).
//   - R10 store policy: default write-back stores (beat __stcs by ~0.4us ncu;
//     evict-first streaming pays DRAM R/W turnaround).
// Plus R7's guard-free exact grid and 4-deep load prologue, IEEE sqrtf.
// 4 rows/thread rolling 3-vector window, warp-shuffle horizontal neighbors.
//
// Layout: W4 = 64 float4 per row, H = 256 rows, plane = 2^14 float4.

static constexpr int W4 = 64;

__global__ __launch_bounds__(256, 8)
void sobel_grad_mag_r13(const float4* __restrict__ in,
                        float4* __restrict__ out)
{
    const int t = blockIdx.x * blockDim.x + threadIdx.x;

    const int lane = threadIdx.x & 31;
    const int col4 = t & (W4 - 1);
    const int rq   = (t >> 6) & 63;                 // rows 4*rq .. 4*rq+3
    const int i0   = ((t >> 12) << 14) | (rq << 8) | col4;

    const float4 zero = make_float4(0.f, 0.f, 0.f, 0.f);
    const float* sc = reinterpret_cast<const float*>(in);
    const float EPS = 1e-6f;
    const bool need_l = (lane == 0)  && (col4 != 0);
    const bool need_r = (lane == 31) && (col4 != W4 - 1);

    // prologue: 4 front-issued loads (up, c, dn, first nxt)
    float4 up  = (rq == 0) ? zero : __ldg(&in[i0 - W4]);
    float4 c   = __ldg(&in[i0]);
    float4 dn  = __ldg(&in[i0 + W4]);
    float4 nx0 = __ldg(&in[i0 + 2 * W4]);

    #pragma unroll
    for (int k = 0; k < 4; k++) {
        float4 nxt;
        if (k == 0) {
            nxt = nx0;
        } else if (k < 3) {
            nxt = (k == 2 && rq == 63) ? zero : __ldg(&in[i0 + (k + 2) * W4]);
        }

        // horizontal neighbors from adjacent lanes (same row vector)
        float l = __shfl_up_sync(0xffffffffu, c.w, 1);
        float r = __shfl_down_sync(0xffffffffu, c.x, 1);
        if (lane == 0)
            l = need_l ? sc[(size_t)(i0 + k * W4) * 4 - 1] : 0.f;
        if (lane == 31)
            r = need_r ? sc[(size_t)(i0 + k * W4) * 4 + 4] : 0.f;

        const float gv0 = dn.x - up.x;
        const float gv1 = dn.y - up.y;
        const float gv2 = dn.z - up.z;
        const float gv3 = dn.w - up.w;

        const float gh0 = c.y - l;
        const float gh1 = c.z - c.x;
        const float gh2 = c.w - c.y;
        const float gh3 = r   - c.z;

        float4 res;
        res.x = sqrtf(fmaf(gv0, gv0, fmaf(gh0, gh0, EPS)));
        res.y = sqrtf(fmaf(gv1, gv1, fmaf(gh1, gh1, EPS)));
        res.z = sqrtf(fmaf(gv2, gv2, fmaf(gh2, gh2, EPS)));
        res.w = sqrtf(fmaf(gv3, gv3, fmaf(gh3, gh3, EPS)));

        out[i0 + k * W4] = res;   // write-back store (measured best)

        // rotate window
        up = c;
        c  = dn;
        if (k < 3) dn = nxt;
    }
}

extern "C" void kernel_launch(void* const* d_in, const int* in_sizes, int n_in,
                              void* d_out, int out_size)
{
    const float4* x = reinterpret_cast<const float4*>(d_in[0]);
    float4* o       = reinterpret_cast<float4*>(d_out);

    // total float4 outputs = out_size/4; each thread produces 4 of them
    int nthreads = out_size / 16;   // 2,097,152 (exactly 8192 * 256)
    int threads  = 256;
    int blocks   = nthreads / threads;

    sobel_grad_mag_r13<<<blocks, threads>>>(x, o);
}

// round 14
// speedup vs baseline: 1.0036x; 1.0036x over previous
#include <cuda_runtime.h>
#include <cuda_bf16.h>
#include <cstdint>

// Sobel gradient magnitude, zero-padded, on [B=8, C=64, H=256, W=256] fp32.
// out = sqrt(gv^2 + gh^2 + 1e-6), gv = x[i+1,j]-x[i-1,j], gh = x[i,j+1]-x[i,j-1].
//
// Round 14: pure launch-shape experiment. On-device time is pinned at
// ~36.5-36.7us for every plateau variant, but WALL time tracks CTA count:
//   8192 CTAs (256thr): 44.6-45.1us   4096 CTAs (512thr): 43.5us x3
// Try 2048 CTAs (1024 threads/block, __launch_bounds__(1024, 2) -> same
// 64 warps/SM, same 32 regs, identical per-thread code as the R10 winner).
//
// Layout: W4 = 64 float4 per row, H = 256 rows, plane = 2^14 float4.

static constexpr int W4 = 64;

__global__ __launch_bounds__(1024, 2)
void sobel_grad_mag_r14(const float4* __restrict__ in,
                        float4* __restrict__ out)
{
    const int t = blockIdx.x * blockDim.x + threadIdx.x;

    const int lane = threadIdx.x & 31;
    const int col4 = t & (W4 - 1);
    const int rq   = (t >> 6) & 63;                 // rows 4*rq .. 4*rq+3
    const int i0   = ((t >> 12) << 14) | (rq << 8) | col4;

    const float4 zero = make_float4(0.f, 0.f, 0.f, 0.f);
    const float* sc = reinterpret_cast<const float*>(in);
    const float EPS = 1e-6f;
    const bool need_l = (lane == 0)  && (col4 != 0);
    const bool need_r = (lane == 31) && (col4 != W4 - 1);

    // prologue: 4 front-issued loads (up, c, dn, first nxt)
    float4 up  = (rq == 0) ? zero : __ldg(&in[i0 - W4]);
    float4 c   = __ldg(&in[i0]);
    float4 dn  = __ldg(&in[i0 + W4]);
    float4 nx0 = __ldg(&in[i0 + 2 * W4]);

    #pragma unroll
    for (int k = 0; k < 4; k++) {
        float4 nxt;
        if (k == 0) {
            nxt = nx0;
        } else if (k < 3) {
            nxt = (k == 2 && rq == 63) ? zero : __ldg(&in[i0 + (k + 2) * W4]);
        }

        // horizontal neighbors from adjacent lanes (same row vector)
        float l = __shfl_up_sync(0xffffffffu, c.w, 1);
        float r = __shfl_down_sync(0xffffffffu, c.x, 1);
        if (lane == 0)
            l = need_l ? sc[(size_t)(i0 + k * W4) * 4 - 1] : 0.f;
        if (lane == 31)
            r = need_r ? sc[(size_t)(i0 + k * W4) * 4 + 4] : 0.f;

        const float gv0 = dn.x - up.x;
        const float gv1 = dn.y - up.y;
        const float gv2 = dn.z - up.z;
        const float gv3 = dn.w - up.w;

        const float gh0 = c.y - l;
        const float gh1 = c.z - c.x;
        const float gh2 = c.w - c.y;
        const float gh3 = r   - c.z;

        float4 res;
        res.x = sqrtf(fmaf(gv0, gv0, fmaf(gh0, gh0, EPS)));
        res.y = sqrtf(fmaf(gv1, gv1, fmaf(gh1, gh1, EPS)));
        res.z = sqrtf(fmaf(gv2, gv2, fmaf(gh2, gh2, EPS)));
        res.w = sqrtf(fmaf(gv3, gv3, fmaf(gh3, gh3, EPS)));

        out[i0 + k * W4] = res;   // write-back store (measured best)

        // rotate window
        up = c;
        c  = dn;
        if (k < 3) dn = nxt;
    }
}

extern "C" void kernel_launch(void* const* d_in, const int* in_sizes, int n_in,
                              void* d_out, int out_size)
{
    const float4* x = reinterpret_cast<const float4*>(d_in[0]);
    float4* o       = reinterpret_cast<float4*>(d_out);

    // total float4 outputs = out_size/4; each thread produces 4 of them
    int nthreads = out_size / 16;   // 2,097,152 (exactly 2048 * 1024)
    int threads  = 1024;
    int blocks   = nthreads / threads;

    sobel_grad_mag_r14<<<blocks, threads>>>(x, o);
}

// round 15
// speedup vs baseline: 1.0338x; 1.0302x over previous
#include <cuda_runtime.h>
#include <cuda_bf16.h>
#include <cstdint>

// Sobel gradient magnitude, zero-padded, on [B=8, C=64, H=256, W=256] fp32.
// out = sqrt(gv^2 + gh^2 + 1e-6), gv = x[i+1,j]-x[i-1,j], gh = x[i,j+1]-x[i,j-1].
//
// FINAL (R10, thrice-benched: 43.52 / 43.55 / this run).
// 512-thread blocks (interior optimum of the shape curve: 256thr -> 44.6-45.1,
// 512thr -> 43.5, 1024thr -> 44.8 wall), 4 rows/thread with a rolling 3-vector
// register window (32 regs), warp-shuffle horizontal neighbors with predicated
// lane-0/31 edge loads, default write-back stores (beat __stcs: evict-first
// pays DRAM R/W turnaround), IEEE sqrtf (approx was pipe-free but wall-neutral),
// exact guard-free grid.
//
// Plateau analysis: 256 MB mandatory traffic at ~5.8 TB/s effective (73% of
// 8 TB/s spec) = mixed read/write HBM3e turnaround ceiling. Rejected along the
// way: 8-row blocking (dep chains), persistent grid (serialized memory issue),
// 2-strip full-row warps (reg pressure + L1 wavefront inflation).
//
// Layout: W4 = 64 float4 per row, H = 256 rows, plane = 2^14 float4.

static constexpr int W4 = 64;

__global__ __launch_bounds__(512, 4)
void sobel_grad_mag_final(const float4* __restrict__ in,
                          float4* __restrict__ out)
{
    const int t = blockIdx.x * blockDim.x + threadIdx.x;

    const int lane = threadIdx.x & 31;
    const int col4 = t & (W4 - 1);
    const int rq   = (t >> 6) & 63;                 // rows 4*rq .. 4*rq+3
    const int i0   = ((t >> 12) << 14) | (rq << 8) | col4;

    const float4 zero = make_float4(0.f, 0.f, 0.f, 0.f);
    const float* sc = reinterpret_cast<const float*>(in);
    const float EPS = 1e-6f;
    const bool need_l = (lane == 0)  && (col4 != 0);
    const bool need_r = (lane == 31) && (col4 != W4 - 1);

    // prologue: 4 front-issued loads (up, c, dn, first nxt)
    float4 up  = (rq == 0) ? zero : __ldg(&in[i0 - W4]);
    float4 c   = __ldg(&in[i0]);
    float4 dn  = __ldg(&in[i0 + W4]);
    float4 nx0 = __ldg(&in[i0 + 2 * W4]);

    #pragma unroll
    for (int k = 0; k < 4; k++) {
        float4 nxt;
        if (k == 0) {
            nxt = nx0;
        } else if (k < 3) {
            nxt = (k == 2 && rq == 63) ? zero : __ldg(&in[i0 + (k + 2) * W4]);
        }

        // horizontal neighbors from adjacent lanes (same row vector)
        float l = __shfl_up_sync(0xffffffffu, c.w, 1);
        float r = __shfl_down_sync(0xffffffffu, c.x, 1);
        if (lane == 0)
            l = need_l ? sc[(size_t)(i0 + k * W4) * 4 - 1] : 0.f;
        if (lane == 31)
            r = need_r ? sc[(size_t)(i0 + k * W4) * 4 + 4] : 0.f;

        const float gv0 = dn.x - up.x;
        const float gv1 = dn.y - up.y;
        const float gv2 = dn.z - up.z;
        const float gv3 = dn.w - up.w;

        const float gh0 = c.y - l;
        const float gh1 = c.z - c.x;
        const float gh2 = c.w - c.y;
        const float gh3 = r   - c.z;

        float4 res;
        res.x = sqrtf(fmaf(gv0, gv0, fmaf(gh0, gh0, EPS)));
        res.y = sqrtf(fmaf(gv1, gv1, fmaf(gh1, gh1, EPS)));
        res.z = sqrtf(fmaf(gv2, gv2, fmaf(gh2, gh2, EPS)));
        res.w = sqrtf(fmaf(gv3, gv3, fmaf(gh3, gh3, EPS)));

        out[i0 + k * W4] = res;   // write-back store (measured best)

        // rotate window
        up = c;
        c  = dn;
        if (k < 3) dn = nxt;
    }
}

extern "C" void kernel_launch(void* const* d_in, const int* in_sizes, int n_in,
                              void* d_out, int out_size)
{
    const float4* x = reinterpret_cast<const float4*>(d_in[0]);
    float4* o       = reinterpret_cast<float4*>(d_out);

    // total float4 outputs = out_size/4; each thread produces 4 of them
    int nthreads = out_size / 16;   // 2,097,152 (exactly 4096 * 512)
    int threads  = 512;
    int blocks   = nthreads / threads;

    sobel_grad_mag_final<<<blocks, threads>>>(x, o);
}